// round 2
// baseline (speedup 1.0000x reference)
#include <cuda_runtime.h>

// LeakyCascade: s[t] = a*s[t-1] + (1-a)*x[t],  a = exp(-dt/tau_m)
// B=8, T=4096, D=256, M=8.
// Blocked scan over T; each block handles ALL M for one (b, chunk) so x is
// read once, not 8x.

#define BB 8
#define TT 4096
#define DD 256
#define MM 8
#define CC 64            // chunks along T
#define LL (TT / CC)     // 64 steps per chunk
#define D4 (DD / 4)      // 64 float4 lanes per (b,t,m) row
#define NTHR (MM * D4)   // 512 threads: tid/64 = m, tid%64 = d-lane

// Scratch (static device globals — no allocation in kernel_launch)
// Layout [B][C][M][D] so phase2 (thread = (b,m,d)) reads coalesced in d.
__device__ float g_send[BB * CC * MM * DD];  // local chunk end-states (4 MB)
__device__ float g_sin [BB * CC * MM * DD];  // true chunk start-states (4 MB)
__device__ float g_A   [BB * CC * MM];       // per-chunk total decay

// ---------------------------------------------------------------------------
// Phase 1: per-chunk local scan from s=0 ; emit s_end and chunk decay A.
// grid = (C, B), block = 512
// ---------------------------------------------------------------------------
__global__ void __launch_bounds__(NTHR) lc_phase1(
    const float* __restrict__ x, const float* __restrict__ delta,
    const float* __restrict__ tau)
{
    const int c = blockIdx.x, b = blockIdx.y;
    const int tid  = threadIdx.x;
    const int m    = tid >> 6;
    const int lane = tid & 63;

    __shared__ float s_alpha[MM][LL];
    __shared__ float s_dtsum[2];

    const float inv_tau = 1.0f / tau[m];
    const int t0 = c * LL;
    const float* drow = delta + b * TT;

    // Each m-group (64 threads) stages its own alphas; i == lane since LL==64.
    {
        const int t = t0 + lane;
        float dt = (t == 0) ? 0.0f : fmaxf(drow[t] - drow[t - 1], 0.0f);
        s_alpha[m][lane] = expf(-dt * inv_tau);
        // m-group 0 also reduces the (m-independent) dt sum for chunk decay.
        if (m == 0) {
            float dsum = dt;
            #pragma unroll
            for (int off = 16; off > 0; off >>= 1)
                dsum += __shfl_down_sync(0xffffffffu, dsum, off);
            if ((lane & 31) == 0) s_dtsum[lane >> 5] = dsum;
        }
    }
    __syncthreads();

    // Local scan from zero state; 8 m-groups share the x chunk via L1.
    float4 s = make_float4(0.f, 0.f, 0.f, 0.f);
    const float4* xp = (const float4*)x + (b * TT + t0) * D4 + lane;
    #pragma unroll 8
    for (int i = 0; i < LL; i++) {
        const float a  = s_alpha[m][i];
        const float om = 1.0f - a;
        const float4 xv = xp[i * D4];
        s.x = fmaf(a, s.x, om * xv.x);
        s.y = fmaf(a, s.y, om * xv.y);
        s.z = fmaf(a, s.z, om * xv.z);
        s.w = fmaf(a, s.w, om * xv.w);
    }

    const int bcm = (b * CC + c) * MM + m;
    ((float4*)g_send)[bcm * D4 + lane] = s;
    if (tid < MM)
        g_A[(b * CC + c) * MM + tid] =
            expf(-(s_dtsum[0] + s_dtsum[1]) / tau[tid]);
}

// ---------------------------------------------------------------------------
// Phase 2: sequential scan across chunks per (b,m,d):
//   s_in[c] = s;  s = A[c]*s + s_end[c]
// 16384 threads; coalesced in d; scratch is L2-resident.
// ---------------------------------------------------------------------------
__global__ void __launch_bounds__(256) lc_phase2()
{
    const int idx = blockIdx.x * blockDim.x + threadIdx.x;  // (b*M+m)*D + d
    const int d  = idx % DD;
    const int bm = idx / DD;
    const int m  = bm % MM;
    const int b  = bm / MM;

    float s = 0.0f;
    #pragma unroll
    for (int c = 0; c < CC; c++) {
        const int base = ((b * CC + c) * MM + m) * DD + d;
        g_sin[base] = s;
        s = fmaf(g_A[(b * CC + c) * MM + m], s, g_send[base]);
    }
}

// ---------------------------------------------------------------------------
// Phase 3: re-scan each chunk from its true s_in and stream the output.
// grid = (C, B), block = 512. Each t-step stores one contiguous 8 KB row.
// ---------------------------------------------------------------------------
__global__ void __launch_bounds__(NTHR) lc_phase3(
    const float* __restrict__ x, const float* __restrict__ delta,
    const float* __restrict__ tau, float* __restrict__ out)
{
    const int c = blockIdx.x, b = blockIdx.y;
    const int tid  = threadIdx.x;
    const int m    = tid >> 6;
    const int lane = tid & 63;

    __shared__ float s_alpha[MM][LL];

    const float inv_tau = 1.0f / tau[m];
    const int t0 = c * LL;
    const float* drow = delta + b * TT;

    {
        const int t = t0 + lane;
        float dt = (t == 0) ? 0.0f : fmaxf(drow[t] - drow[t - 1], 0.0f);
        s_alpha[m][lane] = expf(-dt * inv_tau);
    }
    __syncthreads();

    const int bcm = (b * CC + c) * MM + m;
    float4 s = ((const float4*)g_sin)[bcm * D4 + lane];

    const float4* xp = (const float4*)x + (b * TT + t0) * D4 + lane;
    // out[(b,t,m,d)] as float4: ((b*TT+t)*MM + m)*D4 + lane
    float4* op = (float4*)out + ((b * TT + t0) * MM + m) * D4 + lane;

    #pragma unroll 8
    for (int i = 0; i < LL; i++) {
        const float a  = s_alpha[m][i];
        const float om = 1.0f - a;
        const float4 xv = xp[i * D4];
        s.x = fmaf(a, s.x, om * xv.x);
        s.y = fmaf(a, s.y, om * xv.y);
        s.z = fmaf(a, s.z, om * xv.z);
        s.w = fmaf(a, s.w, om * xv.w);
        op[i * (MM * D4)] = s;
    }
}

// ---------------------------------------------------------------------------
extern "C" void kernel_launch(void* const* d_in, const int* in_sizes, int n_in,
                              void* d_out, int out_size)
{
    const float* x     = (const float*)d_in[0];
    const float* delta = (const float*)d_in[1];
    const float* tau   = (const float*)d_in[2];
    float* out = (float*)d_out;

    dim3 grid(CC, BB);
    lc_phase1<<<grid, NTHR>>>(x, delta, tau);
    lc_phase2<<<64, 256>>>();
    lc_phase3<<<grid, NTHR>>>(x, delta, tau, out);
}